// round 3
// baseline (speedup 1.0000x reference)
#include <cuda_runtime.h>
#include <cuda_bf16.h>

// Jones 4-pol congruence: V_p[a,d,n,t,f] = sum_{b,c} J[a,b,ant1[n],t,f] *
//                         V_m[b,c,n,t,f] * J[d,c,ant2[n],t,f]
// Layouts (row-major): V_m (2,2,NBL,T,F), jones (2,2,NANT,T,F), out (2,2,NBL,T,F)
// HBM-bound streaming kernel.
// R2: L2 policy hints (V_m/out stream-once via .cs, Jones L2-resident) -> traffic
//     at compulsory floor (~1.03 GB).
// R3: occupancy push — __launch_bounds__(256, 6) forces <=42 regs -> 48 warps/SM
//     theoretical, more in-flight loads to hide DRAM latency.

#define NPOL   2
#define NANT   64
#define NBL    2016
#define NTIMES 64
#define NFREQS 256

#define TF      (NTIMES * NFREQS)   // 16384
#define TF4     (TF / 4)            // 4096 float4 groups per baseline
#define SPLANE  (NBL * TF)          // 33,030,144  (V_m / out plane stride)
#define SJPLANE (NANT * TF)         // 1,048,576   (jones plane stride)
#define NGROUPS (NBL * TF4)         // 8,257,536 threads

__device__ __forceinline__ float4 ldcs4(const float* p) {
    return __ldcs((const float4*)p);
}
__device__ __forceinline__ float4 ldg4(const float* p) {
    return __ldg((const float4*)p);
}
__device__ __forceinline__ void stcs4(float* p, float4 v) {
    __stcs((float4*)p, v);
}

__global__ __launch_bounds__(256, 6) void jones_congruence_kernel(
    const float* __restrict__ Vm,
    const float* __restrict__ J,
    const int*   __restrict__ ant1,
    const int*   __restrict__ ant2,
    float*       __restrict__ out)
{
    int idx = blockIdx.x * blockDim.x + threadIdx.x;
    if (idx >= NGROUPS) return;

    int n    = idx >> 12;               // baseline (TF4 = 4096 = 2^12)
    int tf   = (idx & (TF4 - 1)) << 2;  // element offset within plane

    int base = n * TF + tf;             // V_m / out offset within a plane
    int a1   = __ldg(&ant1[n]);
    int a2   = __ldg(&ant2[n]);
    int jb1  = a1 * TF + tf;
    int jb2  = a2 * TF + tf;

    // V_m planes: [b][c] -> plane b*2+c   (stream-once: evict-first)
    float4 v00 = ldcs4(Vm + 0 * SPLANE + base);
    float4 v01 = ldcs4(Vm + 1 * SPLANE + base);
    float4 v10 = ldcs4(Vm + 2 * SPLANE + base);
    float4 v11 = ldcs4(Vm + 3 * SPLANE + base);

    // j1 = jones[:, :, ant1[n]]   (L2-resident: cache-all)
    float4 a00 = ldg4(J + 0 * SJPLANE + jb1);
    float4 a01 = ldg4(J + 1 * SJPLANE + jb1);
    float4 a10 = ldg4(J + 2 * SJPLANE + jb1);
    float4 a11 = ldg4(J + 3 * SJPLANE + jb1);

    // j2 = jones[:, :, ant2[n]]
    float4 b00 = ldg4(J + 0 * SJPLANE + jb2);
    float4 b01 = ldg4(J + 1 * SJPLANE + jb2);
    float4 b10 = ldg4(J + 2 * SJPLANE + jb2);
    float4 b11 = ldg4(J + 3 * SJPLANE + jb2);

    float4 o00, o01, o10, o11;

    // M = J1 @ V ; O[a][d] = sum_c M[a][c] * J2[d][c]   (real inputs -> conj = id)
#define JONES_LANE(s)                                                   \
    {                                                                   \
        float m00 = a00.s * v00.s + a01.s * v10.s;                      \
        float m01 = a00.s * v01.s + a01.s * v11.s;                      \
        float m10 = a10.s * v00.s + a11.s * v10.s;                      \
        float m11 = a10.s * v01.s + a11.s * v11.s;                      \
        o00.s = m00 * b00.s + m01 * b01.s;                              \
        o01.s = m00 * b10.s + m01 * b11.s;                              \
        o10.s = m10 * b00.s + m11 * b01.s;                              \
        o11.s = m10 * b10.s + m11 * b11.s;                              \
    }

    JONES_LANE(x)
    JONES_LANE(y)
    JONES_LANE(z)
    JONES_LANE(w)
#undef JONES_LANE

    // out planes: [a][d] -> plane a*2+d   (write-once: streaming stores)
    stcs4(out + 0 * SPLANE + base, o00);
    stcs4(out + 1 * SPLANE + base, o01);
    stcs4(out + 2 * SPLANE + base, o10);
    stcs4(out + 3 * SPLANE + base, o11);
}

extern "C" void kernel_launch(void* const* d_in, const int* in_sizes, int n_in,
                              void* d_out, int out_size)
{
    const float* Vm   = (const float*)d_in[0];
    const float* J    = (const float*)d_in[1];
    const int*   ant1 = (const int*)d_in[2];
    const int*   ant2 = (const int*)d_in[3];
    float*       out  = (float*)d_out;

    const int threads = 256;
    const int blocks  = (NGROUPS + threads - 1) / threads;  // 32256
    jones_congruence_kernel<<<blocks, threads>>>(Vm, J, ant1, ant2, out);
}

// round 4
// speedup vs baseline: 1.0689x; 1.0689x over previous
#include <cuda_runtime.h>
#include <cuda_bf16.h>

// Jones 4-pol congruence: V_p[a,d,n,t,f] = sum_{b,c} J[a,b,ant1[n],t,f] *
//                         V_m[b,c,n,t,f] * J[d,c,ant2[n],t,f]
// Layouts (row-major): V_m (2,2,NBL,T,F), jones (2,2,NANT,T,F), out (2,2,NBL,T,F)
// HBM/latency-bound streaming kernel.
// R2: L2 policy hints (.cs for stream-once V_m/out, Jones L2-resident) -> 1.03 GB floor.
// R3 (FAILED): reg squeeze to 40 serialized the load batch -> MLP drop -> regression.
// R4: give ptxas a 64-reg budget (minblocks=4) so all 12 float4 loads stay
//     front-batched -> deeper per-thread MLP, fewer CTAs contending at L1tex.

#define NPOL   2
#define NANT   64
#define NBL    2016
#define NTIMES 64
#define NFREQS 256

#define TF      (NTIMES * NFREQS)   // 16384
#define TF4     (TF / 4)            // 4096 float4 groups per baseline
#define SPLANE  (NBL * TF)          // 33,030,144  (V_m / out plane stride)
#define SJPLANE (NANT * TF)         // 1,048,576   (jones plane stride)
#define NGROUPS (NBL * TF4)         // 8,257,536 threads

__device__ __forceinline__ float4 ldcs4(const float* p) {
    return __ldcs((const float4*)p);
}
__device__ __forceinline__ float4 ldg4(const float* p) {
    return __ldg((const float4*)p);
}
__device__ __forceinline__ void stcs4(float* p, float4 v) {
    __stcs((float4*)p, v);
}

__global__ __launch_bounds__(256, 4) void jones_congruence_kernel(
    const float* __restrict__ Vm,
    const float* __restrict__ J,
    const int*   __restrict__ ant1,
    const int*   __restrict__ ant2,
    float*       __restrict__ out)
{
    int idx = blockIdx.x * blockDim.x + threadIdx.x;
    if (idx >= NGROUPS) return;

    int n    = idx >> 12;               // baseline (TF4 = 4096 = 2^12)
    int tf   = (idx & (TF4 - 1)) << 2;  // element offset within plane

    int base = n * TF + tf;             // V_m / out offset within a plane
    int a1   = __ldg(&ant1[n]);
    int a2   = __ldg(&ant2[n]);
    int jb1  = a1 * TF + tf;
    int jb2  = a2 * TF + tf;

    // ---- front-batch ALL 12 loads (deep MLP) ----
    // V_m planes: [b][c] -> plane b*2+c   (stream-once: evict-first)
    float4 v00 = ldcs4(Vm + 0 * SPLANE + base);
    float4 v01 = ldcs4(Vm + 1 * SPLANE + base);
    float4 v10 = ldcs4(Vm + 2 * SPLANE + base);
    float4 v11 = ldcs4(Vm + 3 * SPLANE + base);

    // j1 = jones[:, :, ant1[n]]   (L2-resident: cache-all)
    float4 a00 = ldg4(J + 0 * SJPLANE + jb1);
    float4 a01 = ldg4(J + 1 * SJPLANE + jb1);
    float4 a10 = ldg4(J + 2 * SJPLANE + jb1);
    float4 a11 = ldg4(J + 3 * SJPLANE + jb1);

    // j2 = jones[:, :, ant2[n]]
    float4 b00 = ldg4(J + 0 * SJPLANE + jb2);
    float4 b01 = ldg4(J + 1 * SJPLANE + jb2);
    float4 b10 = ldg4(J + 2 * SJPLANE + jb2);
    float4 b11 = ldg4(J + 3 * SJPLANE + jb2);

    float4 o00, o01, o10, o11;

    // M = J1 @ V ; O[a][d] = sum_c M[a][c] * J2[d][c]   (real inputs -> conj = id)
#define JONES_LANE(s)                                                   \
    {                                                                   \
        float m00 = a00.s * v00.s + a01.s * v10.s;                      \
        float m01 = a00.s * v01.s + a01.s * v11.s;                      \
        float m10 = a10.s * v00.s + a11.s * v10.s;                      \
        float m11 = a10.s * v01.s + a11.s * v11.s;                      \
        o00.s = m00 * b00.s + m01 * b01.s;                              \
        o01.s = m00 * b10.s + m01 * b11.s;                              \
        o10.s = m10 * b00.s + m11 * b01.s;                              \
        o11.s = m10 * b10.s + m11 * b11.s;                              \
    }

    JONES_LANE(x)
    JONES_LANE(y)
    JONES_LANE(z)
    JONES_LANE(w)
#undef JONES_LANE

    // out planes: [a][d] -> plane a*2+d   (write-once: streaming stores)
    stcs4(out + 0 * SPLANE + base, o00);
    stcs4(out + 1 * SPLANE + base, o01);
    stcs4(out + 2 * SPLANE + base, o10);
    stcs4(out + 3 * SPLANE + base, o11);
}

extern "C" void kernel_launch(void* const* d_in, const int* in_sizes, int n_in,
                              void* d_out, int out_size)
{
    const float* Vm   = (const float*)d_in[0];
    const float* J    = (const float*)d_in[1];
    const int*   ant1 = (const int*)d_in[2];
    const int*   ant2 = (const int*)d_in[3];
    float*       out  = (float*)d_out;

    const int threads = 256;
    const int blocks  = (NGROUPS + threads - 1) / threads;  // 32256
    jones_congruence_kernel<<<blocks, threads>>>(Vm, J, ant1, ant2, out);
}